// round 4
// baseline (speedup 1.0000x reference)
#include <cuda_runtime.h>
#include <cuda_bf16.h>
#include <cstdint>

#define SS 4
#define NN 4096
#define DD 64

// Scratch for Q[s,j,d] = sum_e x0[s,j,e] * W[d,e]  (4 MB, static — no allocs allowed)
__device__ float g_Q[(size_t)SS * NN * DD];

// ---------------------------------------------------------------------------
// Stage 1: Q = x0 @ W^T.  4 threads per row (16 d-outputs each) for parallelism.
// ---------------------------------------------------------------------------
__global__ __launch_bounds__(256) void q_kernel(const float* __restrict__ x0,
                                                const float* __restrict__ W) {
    __shared__ float Ws[DD * DD];
    int tid = threadIdx.x;
    #pragma unroll
    for (int i = tid; i < DD * DD / 4; i += 256)
        ((float4*)Ws)[i] = ((const float4*)W)[i];
    __syncthreads();

    int gid = blockIdx.x * 256 + tid;      // 0 .. 4*S*N-1
    int row = gid >> 2;
    int dq  = gid & 3;                     // d-quarter: 16 outputs

    const float4* xr = (const float4*)(x0 + (size_t)row * DD);
    float4 x[16];
    #pragma unroll
    for (int e = 0; e < 16; ++e) x[e] = xr[e];

    float4* q = (float4*)(g_Q + (size_t)row * DD + dq * 16);
    #pragma unroll
    for (int d4 = 0; d4 < 4; ++d4) {
        float r[4];
        #pragma unroll
        for (int dd = 0; dd < 4; ++dd) {
            int d = dq * 16 + d4 * 4 + dd;
            const float4* wr = (const float4*)(Ws + d * DD);
            float a0 = 0.f, a1 = 0.f, a2 = 0.f, a3 = 0.f;
            #pragma unroll
            for (int e4 = 0; e4 < 16; e4 += 4) {
                float4 w0 = wr[e4 + 0], w1 = wr[e4 + 1], w2 = wr[e4 + 2], w3 = wr[e4 + 3];
                a0 += x[e4 + 0].x * w0.x + x[e4 + 0].y * w0.y + x[e4 + 0].z * w0.z + x[e4 + 0].w * w0.w;
                a1 += x[e4 + 1].x * w1.x + x[e4 + 1].y * w1.y + x[e4 + 1].z * w1.z + x[e4 + 1].w * w1.w;
                a2 += x[e4 + 2].x * w2.x + x[e4 + 2].y * w2.y + x[e4 + 2].z * w2.z + x[e4 + 2].w * w2.w;
                a3 += x[e4 + 3].x * w3.x + x[e4 + 3].y * w3.y + x[e4 + 3].z * w3.z + x[e4 + 3].w * w3.w;
            }
            r[dd] = (a0 + a1) + (a2 + a3);
        }
        q[d4] = make_float4(r[0], r[1], r[2], r[3]);
    }
}

// ---------------------------------------------------------------------------
// Baseline-PTX tensor core helpers
// ---------------------------------------------------------------------------
__device__ __forceinline__ uint32_t smem_u32(const void* p) {
    uint32_t a;
    asm("{ .reg .u64 t; cvta.to.shared.u64 t, %1; cvt.u32.u64 %0, t; }" : "=r"(a) : "l"(p));
    return a;
}

__device__ __forceinline__ void ldsm4(uint32_t* r, uint32_t addr) {
    asm volatile("ldmatrix.sync.aligned.m8n8.x4.shared.b16 {%0,%1,%2,%3}, [%4];"
                 : "=r"(r[0]), "=r"(r[1]), "=r"(r[2]), "=r"(r[3]) : "r"(addr));
}

__device__ __forceinline__ void mma16816(float* c, const uint32_t* a,
                                         const uint32_t* b) {
    asm volatile(
        "mma.sync.aligned.m16n8k16.row.col.f32.bf16.bf16.f32 "
        "{%0,%1,%2,%3}, {%4,%5,%6,%7}, {%8,%9}, {%0,%1,%2,%3};"
        : "+f"(c[0]), "+f"(c[1]), "+f"(c[2]), "+f"(c[3])
        : "r"(a[0]), "r"(a[1]), "r"(a[2]), "r"(a[3]), "r"(b[0]), "r"(b[1]));
}

// SMEM: 4 tiles of 128 rows x 72 bf16 (pitch 144B -> conflict-free ldmatrix)
#define PITCHB 144
#define TILEB  (128 * PITCHB)   // 18432
#define SM_AH  0
#define SM_AL  TILEB
#define SM_BH  (2 * TILEB)
#define SM_BL  (3 * TILEB)
#define SM_TOTAL (4 * TILEB)    // 73728 B
#define OPITCH 132              // epilogue fp32 tile pitch (128+4) -> 66 KB, fits

// ---------------------------------------------------------------------------
// Stage 2: out[s,i,j] = sum_d x1[s,i,d] * Q[s,j,d] via bf16x3 mma.sync.
// 128x128 tile/CTA, 8 warps (4x2), warp tile 32x64, K=64 resident.
// ---------------------------------------------------------------------------
__global__ __launch_bounds__(256, 2) void gemm_mma(const float* __restrict__ x1,
                                                   const float* __restrict__ bias,
                                                   float* __restrict__ out) {
    extern __shared__ char smem[];
    const uint32_t sb = smem_u32(smem);
    const int tid = threadIdx.x, wid = tid >> 5, lid = tid & 31;
    const int s = blockIdx.z, bi = blockIdx.y, bj = blockIdx.x;
    const int warp_m = wid >> 1;   // 0..3, 32 rows
    const int warp_n = wid & 1;    // 0..1, 64 cols

    // ---- Load + split-convert both 128x64 fp32 tiles to bf16 hi/lo ----
    const float4* Ag = (const float4*)(x1 + ((size_t)s * NN + (size_t)bi * 128) * DD);
    const float4* Bg = (const float4*)(g_Q + ((size_t)s * NN + (size_t)bj * 128) * DD);

    #pragma unroll
    for (int half = 0; half < 2; ++half) {
        const float4* G = half ? Bg : Ag;
        char* sh = smem + (half ? SM_BH : SM_AH);
        char* sl = smem + (half ? SM_BL : SM_AL);
        #pragma unroll
        for (int it = 0; it < 4; ++it) {
            int idx = it * 256 + tid;
            int row = idx >> 3;
            int c8  = idx & 7;
            float4 v0 = G[row * 16 + c8 * 2];
            float4 v1 = G[row * 16 + c8 * 2 + 1];
            float f[8] = {v0.x, v0.y, v0.z, v0.w, v1.x, v1.y, v1.z, v1.w};
            uint32_t h[4], l[4];
            #pragma unroll
            for (int p = 0; p < 4; ++p) {
                float a = f[2 * p], b = f[2 * p + 1];
                __nv_bfloat16 ah = __float2bfloat16(a), bh = __float2bfloat16(b);
                float ar = a - __bfloat162float(ah);
                float br = b - __bfloat162float(bh);
                __nv_bfloat162 hp; hp.x = ah; hp.y = bh;
                __nv_bfloat162 lp = __floats2bfloat162_rn(ar, br);
                h[p] = *(uint32_t*)&hp;
                l[p] = *(uint32_t*)&lp;
            }
            uint32_t off = (uint32_t)(row * PITCHB + c8 * 16);
            *(uint4*)(sh + off) = make_uint4(h[0], h[1], h[2], h[3]);
            *(uint4*)(sl + off) = make_uint4(l[0], l[1], l[2], l[3]);
        }
    }
    __syncthreads();

    // ---- Per-lane ldmatrix base addresses ----
    const uint32_t a_lane = (uint32_t)((warp_m * 32 + (lid & 15)) * PITCHB +
                                       ((lid >> 4) * 8) * 2);
    const uint32_t b_lane = (uint32_t)((warp_n * 64 + ((lid >> 4) & 1) * 8 + (lid & 7)) * PITCHB +
                                       (((lid >> 3) & 1) * 8) * 2);

    float acc[2][8][4];
    #pragma unroll
    for (int mt = 0; mt < 2; ++mt)
        #pragma unroll
        for (int nt = 0; nt < 8; ++nt)
            #pragma unroll
            for (int r = 0; r < 4; ++r) acc[mt][nt][r] = 0.f;

    const uint32_t pAh = sb + SM_AH + a_lane, pAl = sb + SM_AL + a_lane;
    const uint32_t pBh = sb + SM_BH + b_lane, pBl = sb + SM_BL + b_lane;

    // ---- Mainloop with fragment reuse: Ah*Bh, Al*Bh, Ah*Bl per k-step ----
    #pragma unroll
    for (int ks = 0; ks < 4; ++ks) {
        const uint32_t ko = (uint32_t)(ks * 32);
        uint32_t ah[2][4], al[2][4], bh[4][4], bl[4][4];
        #pragma unroll
        for (int mt = 0; mt < 2; ++mt)
            ldsm4(ah[mt], pAh + (uint32_t)(mt * 16 * PITCHB) + ko);
        #pragma unroll
        for (int nq = 0; nq < 4; ++nq)
            ldsm4(bh[nq], pBh + (uint32_t)(nq * 16 * PITCHB) + ko);
        #pragma unroll
        for (int mt = 0; mt < 2; ++mt)
            #pragma unroll
            for (int nq = 0; nq < 4; ++nq) {
                mma16816(acc[mt][2 * nq],     ah[mt], &bh[nq][0]);
                mma16816(acc[mt][2 * nq + 1], ah[mt], &bh[nq][2]);
            }
        #pragma unroll
        for (int mt = 0; mt < 2; ++mt)
            ldsm4(al[mt], pAl + (uint32_t)(mt * 16 * PITCHB) + ko);
        #pragma unroll
        for (int mt = 0; mt < 2; ++mt)
            #pragma unroll
            for (int nq = 0; nq < 4; ++nq) {
                mma16816(acc[mt][2 * nq],     al[mt], &bh[nq][0]);
                mma16816(acc[mt][2 * nq + 1], al[mt], &bh[nq][2]);
            }
        #pragma unroll
        for (int nq = 0; nq < 4; ++nq)
            ldsm4(bl[nq], pBl + (uint32_t)(nq * 16 * PITCHB) + ko);
        #pragma unroll
        for (int mt = 0; mt < 2; ++mt)
            #pragma unroll
            for (int nq = 0; nq < 4; ++nq) {
                mma16816(acc[mt][2 * nq],     ah[mt], &bl[nq][0]);
                mma16816(acc[mt][2 * nq + 1], ah[mt], &bl[nq][2]);
            }
    }

    // ---- Epilogue: smem transpose -> fully coalesced float4 stores ----
    __syncthreads();                      // operand smem now dead
    float* tb = (float*)smem;
    {
        const int r0 = warp_m * 32 + (lid >> 2);
        const int c0 = warp_n * 64 + (lid & 3) * 2;
        #pragma unroll
        for (int mt = 0; mt < 2; ++mt)
            #pragma unroll
            for (int nt = 0; nt < 8; ++nt) {
                float* p = tb + (r0 + mt * 16) * OPITCH + c0 + nt * 8;
                *(float2*)p = make_float2(acc[mt][nt][0], acc[mt][nt][1]);
                *(float2*)(p + 8 * OPITCH) = make_float2(acc[mt][nt][2], acc[mt][nt][3]);
            }
    }
    __syncthreads();

    const float bv = *bias;
    const size_t BST = (size_t)SS * NN * NN;
    #pragma unroll
    for (int it = 0; it < 16; ++it) {
        int idx = it * 256 + tid;          // float4 id, 0..4095
        int row = idx >> 5;
        int c4  = idx & 31;
        float4 v = *(float4*)(tb + row * OPITCH + c4 * 4);
        v.x += bv; v.y += bv; v.z += bv; v.w += bv;
        float* dst = out + ((size_t)s * NN + (size_t)bi * 128 + row) * NN +
                     (size_t)bj * 128 + c4 * 4;
        *(float4*)dst = v;
        *(float4*)(dst + BST) = v;
    }
}

// ---------------------------------------------------------------------------
// Launch
// ---------------------------------------------------------------------------
extern "C" void kernel_launch(void* const* d_in, const int* in_sizes, int n_in,
                              void* d_out, int out_size) {
    const float* x0   = (const float*)d_in[0];  // tensor0 (S,N,D)
    const float* x1   = (const float*)d_in[1];  // tensor1 (S,N,D)
    const float* W    = (const float*)d_in[2];  // kernel (D,D)
    const float* bias = (const float*)d_in[3];  // scalar
    float* out = (float*)d_out;                 // (2,S,N,N)

    q_kernel<<<(4 * SS * NN) / 256, 256>>>(x0, W);

    cudaFuncSetAttribute(gemm_mma, cudaFuncAttributeMaxDynamicSharedMemorySize, SM_TOTAL);
    dim3 grid(NN / 128, NN / 128, SS);
    gemm_mma<<<grid, 256, SM_TOTAL>>>(x1, bias, out);
}

// round 5
// speedup vs baseline: 1.2374x; 1.2374x over previous
#include <cuda_runtime.h>
#include <cuda_bf16.h>
#include <cstdint>

#define SS 4
#define NN 4096
#define DD 64

// Scratch for Q[s,j,d] = sum_e x0[s,j,e] * W[d,e]  (4 MB, static — no allocs allowed)
__device__ float g_Q[(size_t)SS * NN * DD];

// ---------------------------------------------------------------------------
// Stage 1: Q = x0 @ W^T.  2 threads per row (32 d-outputs each): 128 CTAs.
// ---------------------------------------------------------------------------
__global__ __launch_bounds__(256) void q_kernel(const float* __restrict__ x0,
                                                const float* __restrict__ W) {
    __shared__ float Ws[DD * DD];
    int tid = threadIdx.x;
    #pragma unroll
    for (int i = tid; i < DD * DD / 4; i += 256)
        ((float4*)Ws)[i] = ((const float4*)W)[i];
    __syncthreads();

    int gid = blockIdx.x * 256 + tid;      // 0 .. 2*S*N-1
    int row = gid >> 1;
    int half = gid & 1;                    // 32 d-outputs

    const float4* xr = (const float4*)(x0 + (size_t)row * DD);
    float4 x[16];
    #pragma unroll
    for (int e = 0; e < 16; ++e) x[e] = xr[e];

    float4* q = (float4*)(g_Q + (size_t)row * DD + half * 32);
    #pragma unroll
    for (int d4 = 0; d4 < 8; ++d4) {
        float r[4];
        #pragma unroll
        for (int dd = 0; dd < 4; ++dd) {
            int d = half * 32 + d4 * 4 + dd;
            const float4* wr = (const float4*)(Ws + d * DD);
            float a0 = 0.f, a1 = 0.f, a2 = 0.f, a3 = 0.f;
            #pragma unroll
            for (int e4 = 0; e4 < 16; e4 += 4) {
                float4 w0 = wr[e4 + 0], w1 = wr[e4 + 1], w2 = wr[e4 + 2], w3 = wr[e4 + 3];
                a0 += x[e4 + 0].x * w0.x + x[e4 + 0].y * w0.y + x[e4 + 0].z * w0.z + x[e4 + 0].w * w0.w;
                a1 += x[e4 + 1].x * w1.x + x[e4 + 1].y * w1.y + x[e4 + 1].z * w1.z + x[e4 + 1].w * w1.w;
                a2 += x[e4 + 2].x * w2.x + x[e4 + 2].y * w2.y + x[e4 + 2].z * w2.z + x[e4 + 2].w * w2.w;
                a3 += x[e4 + 3].x * w3.x + x[e4 + 3].y * w3.y + x[e4 + 3].z * w3.z + x[e4 + 3].w * w3.w;
            }
            r[dd] = (a0 + a1) + (a2 + a3);
        }
        q[d4] = make_float4(r[0], r[1], r[2], r[3]);
    }
}

// ---------------------------------------------------------------------------
// Baseline-PTX tensor core helpers
// ---------------------------------------------------------------------------
__device__ __forceinline__ uint32_t smem_u32(const void* p) {
    uint32_t a;
    asm("{ .reg .u64 t; cvta.to.shared.u64 t, %1; cvt.u32.u64 %0, t; }" : "=r"(a) : "l"(p));
    return a;
}

__device__ __forceinline__ void ldsm4(uint32_t* r, uint32_t addr) {
    asm volatile("ldmatrix.sync.aligned.m8n8.x4.shared.b16 {%0,%1,%2,%3}, [%4];"
                 : "=r"(r[0]), "=r"(r[1]), "=r"(r[2]), "=r"(r[3]) : "r"(addr));
}

__device__ __forceinline__ void mma16816(float* c, const uint32_t* a,
                                         const uint32_t* b) {
    asm volatile(
        "mma.sync.aligned.m16n8k16.row.col.f32.bf16.bf16.f32 "
        "{%0,%1,%2,%3}, {%4,%5,%6,%7}, {%8,%9}, {%0,%1,%2,%3};"
        : "+f"(c[0]), "+f"(c[1]), "+f"(c[2]), "+f"(c[3])
        : "r"(a[0]), "r"(a[1]), "r"(a[2]), "r"(a[3]), "r"(b[0]), "r"(b[1]));
}

// Streaming store (evict-first): output is write-once, never re-read.
__device__ __forceinline__ void stcs2(float* p, float2 v) {
    asm volatile("st.global.cs.v2.f32 [%0], {%1,%2};" :: "l"(p), "f"(v.x), "f"(v.y)
                 : "memory");
}

// SMEM: 4 tiles of 128 rows x 72 bf16 (pitch 144B -> conflict-free ldmatrix)
#define PITCHB 144
#define TILEB  (128 * PITCHB)   // 18432
#define SM_AH  0
#define SM_AL  TILEB
#define SM_BH  (2 * TILEB)
#define SM_BL  (3 * TILEB)
#define SM_TOTAL (4 * TILEB)    // 73728 B

// ---------------------------------------------------------------------------
// Stage 2: out[s,i,j] = sum_d x1[s,i,d] * Q[s,j,d] via bf16x3 mma.sync.
// 128x128 tile/CTA, 8 warps (4x2), warp tile 32x64, K=64 resident.
// ---------------------------------------------------------------------------
__global__ __launch_bounds__(256, 2) void gemm_mma(const float* __restrict__ x1,
                                                   const float* __restrict__ bias,
                                                   float* __restrict__ out) {
    extern __shared__ char smem[];
    const uint32_t sb = smem_u32(smem);
    const int tid = threadIdx.x, wid = tid >> 5, lid = tid & 31;
    const int s = blockIdx.z, bi = blockIdx.y, bj = blockIdx.x;
    const int warp_m = wid >> 1;   // 0..3, 32 rows
    const int warp_n = wid & 1;    // 0..1, 64 cols

    // ---- Load + split-convert both 128x64 fp32 tiles to bf16 hi/lo ----
    const float4* Ag = (const float4*)(x1 + ((size_t)s * NN + (size_t)bi * 128) * DD);
    const float4* Bg = (const float4*)(g_Q + ((size_t)s * NN + (size_t)bj * 128) * DD);

    #pragma unroll
    for (int half = 0; half < 2; ++half) {
        const float4* G = half ? Bg : Ag;
        char* sh = smem + (half ? SM_BH : SM_AH);
        char* sl = smem + (half ? SM_BL : SM_AL);
        #pragma unroll
        for (int it = 0; it < 4; ++it) {
            int idx = it * 256 + tid;
            int row = idx >> 3;
            int c8  = idx & 7;
            float4 v0 = G[row * 16 + c8 * 2];
            float4 v1 = G[row * 16 + c8 * 2 + 1];
            float f[8] = {v0.x, v0.y, v0.z, v0.w, v1.x, v1.y, v1.z, v1.w};
            uint32_t h[4], l[4];
            #pragma unroll
            for (int p = 0; p < 4; ++p) {
                float a = f[2 * p], b = f[2 * p + 1];
                __nv_bfloat16 ah = __float2bfloat16(a), bh = __float2bfloat16(b);
                float ar = a - __bfloat162float(ah);
                float br = b - __bfloat162float(bh);
                __nv_bfloat162 hp; hp.x = ah; hp.y = bh;
                __nv_bfloat162 lp = __floats2bfloat162_rn(ar, br);
                h[p] = *(uint32_t*)&hp;
                l[p] = *(uint32_t*)&lp;
            }
            uint32_t off = (uint32_t)(row * PITCHB + c8 * 16);
            *(uint4*)(sh + off) = make_uint4(h[0], h[1], h[2], h[3]);
            *(uint4*)(sl + off) = make_uint4(l[0], l[1], l[2], l[3]);
        }
    }
    __syncthreads();

    // ---- Per-lane ldmatrix base addresses ----
    const uint32_t a_lane = (uint32_t)((warp_m * 32 + (lid & 15)) * PITCHB +
                                       ((lid >> 4) * 8) * 2);
    const uint32_t b_lane = (uint32_t)((warp_n * 64 + ((lid >> 4) & 1) * 8 + (lid & 7)) * PITCHB +
                                       (((lid >> 3) & 1) * 8) * 2);

    float acc[2][8][4];
    #pragma unroll
    for (int mt = 0; mt < 2; ++mt)
        #pragma unroll
        for (int nt = 0; nt < 8; ++nt)
            #pragma unroll
            for (int r = 0; r < 4; ++r) acc[mt][nt][r] = 0.f;

    const uint32_t pAh = sb + SM_AH + a_lane, pAl = sb + SM_AL + a_lane;
    const uint32_t pBh = sb + SM_BH + b_lane, pBl = sb + SM_BL + b_lane;

    // ---- Mainloop with fragment reuse: Ah*Bh, Al*Bh, Ah*Bl per k-step ----
    #pragma unroll
    for (int ks = 0; ks < 4; ++ks) {
        const uint32_t ko = (uint32_t)(ks * 32);
        uint32_t ah[2][4], al[2][4], bh[4][4], bl[4][4];
        #pragma unroll
        for (int mt = 0; mt < 2; ++mt)
            ldsm4(ah[mt], pAh + (uint32_t)(mt * 16 * PITCHB) + ko);
        #pragma unroll
        for (int nq = 0; nq < 4; ++nq)
            ldsm4(bh[nq], pBh + (uint32_t)(nq * 16 * PITCHB) + ko);
        #pragma unroll
        for (int mt = 0; mt < 2; ++mt)
            #pragma unroll
            for (int nq = 0; nq < 4; ++nq) {
                mma16816(acc[mt][2 * nq],     ah[mt], &bh[nq][0]);
                mma16816(acc[mt][2 * nq + 1], ah[mt], &bh[nq][2]);
            }
        #pragma unroll
        for (int mt = 0; mt < 2; ++mt)
            ldsm4(al[mt], pAl + (uint32_t)(mt * 16 * PITCHB) + ko);
        #pragma unroll
        for (int mt = 0; mt < 2; ++mt)
            #pragma unroll
            for (int nq = 0; nq < 4; ++nq) {
                mma16816(acc[mt][2 * nq],     al[mt], &bh[nq][0]);
                mma16816(acc[mt][2 * nq + 1], al[mt], &bh[nq][2]);
            }
        #pragma unroll
        for (int nq = 0; nq < 4; ++nq)
            ldsm4(bl[nq], pBl + (uint32_t)(nq * 16 * PITCHB) + ko);
        #pragma unroll
        for (int mt = 0; mt < 2; ++mt)
            #pragma unroll
            for (int nq = 0; nq < 4; ++nq) {
                mma16816(acc[mt][2 * nq],     ah[mt], &bl[nq][0]);
                mma16816(acc[mt][2 * nq + 1], ah[mt], &bl[nq][2]);
            }
    }

    // ---- Epilogue: direct register stores (streaming), both batch copies ----
    const float bv = *bias;
    const size_t BST = (size_t)SS * NN * NN;
    const size_t i_base = (size_t)bi * 128 + warp_m * 32 + (lid >> 2);
    const size_t j_base = (size_t)bj * 128 + warp_n * 64 + (lid & 3) * 2;

    #pragma unroll
    for (int mt = 0; mt < 2; ++mt) {
        #pragma unroll
        for (int nt = 0; nt < 8; ++nt) {
            float2 v0 = make_float2(acc[mt][nt][0] + bv, acc[mt][nt][1] + bv);
            float2 v1 = make_float2(acc[mt][nt][2] + bv, acc[mt][nt][3] + bv);
            float* d = out + ((size_t)s * NN + i_base + mt * 16) * NN + j_base + nt * 8;
            stcs2(d, v0);
            stcs2(d + 8 * NN, v1);
            stcs2(d + BST, v0);
            stcs2(d + BST + 8 * NN, v1);
        }
    }
}

// ---------------------------------------------------------------------------
// Launch
// ---------------------------------------------------------------------------
extern "C" void kernel_launch(void* const* d_in, const int* in_sizes, int n_in,
                              void* d_out, int out_size) {
    const float* x0   = (const float*)d_in[0];  // tensor0 (S,N,D)
    const float* x1   = (const float*)d_in[1];  // tensor1 (S,N,D)
    const float* W    = (const float*)d_in[2];  // kernel (D,D)
    const float* bias = (const float*)d_in[3];  // scalar
    float* out = (float*)d_out;                 // (2,S,N,N)

    q_kernel<<<(2 * SS * NN) / 256, 256>>>(x0, W);

    cudaFuncSetAttribute(gemm_mma, cudaFuncAttributeMaxDynamicSharedMemorySize, SM_TOTAL);
    dim3 grid(NN / 128, NN / 128, SS);
    gemm_mma<<<grid, 256, SM_TOTAL>>>(x1, bias, out);
}

// round 6
// speedup vs baseline: 1.2488x; 1.0092x over previous
#include <cuda_runtime.h>
#include <cuda_bf16.h>
#include <cstdint>

#define SS 4
#define NN 4096
#define DD 64

// Pre-split bf16 hi/lo operand arrays (2 MB each, static — no allocs allowed)
__device__ __nv_bfloat16 g_Ah[(size_t)SS * NN * DD];
__device__ __nv_bfloat16 g_Al[(size_t)SS * NN * DD];
__device__ __nv_bfloat16 g_Bh[(size_t)SS * NN * DD];
__device__ __nv_bfloat16 g_Bl[(size_t)SS * NN * DD];

__device__ __forceinline__ uint32_t pkbf2(float a, float b) {
    __nv_bfloat162 t = __floats2bfloat162_rn(a, b);
    return *(uint32_t*)&t;
}

// ---------------------------------------------------------------------------
// Stage 1 (fused): blocks [0,128):  Q = x0 @ W^T, split -> g_Bh/g_Bl
//                  blocks [128,192): split x1 -> g_Ah/g_Al
// ---------------------------------------------------------------------------
__global__ __launch_bounds__(256) void prep_kernel(const float* __restrict__ x0,
                                                   const float* __restrict__ x1,
                                                   const float* __restrict__ W) {
    const int tid = threadIdx.x;
    if (blockIdx.x < 128) {
        __shared__ float Ws[DD * DD];
        #pragma unroll
        for (int i = tid; i < DD * DD / 4; i += 256)
            ((float4*)Ws)[i] = ((const float4*)W)[i];
        __syncthreads();

        int gid = blockIdx.x * 256 + tid;      // 0 .. 2*S*N-1
        int row = gid >> 1;
        int half = gid & 1;                    // 32 d-outputs

        const float4* xr = (const float4*)(x0 + (size_t)row * DD);
        float4 x[16];
        #pragma unroll
        for (int e = 0; e < 16; ++e) x[e] = xr[e];

        uint2* qh = (uint2*)(g_Bh + (size_t)row * DD + half * 32);
        uint2* ql = (uint2*)(g_Bl + (size_t)row * DD + half * 32);
        #pragma unroll
        for (int d4 = 0; d4 < 8; ++d4) {
            float r[4];
            #pragma unroll
            for (int dd = 0; dd < 4; ++dd) {
                int d = half * 32 + d4 * 4 + dd;
                const float4* wr = (const float4*)(Ws + d * DD);
                float a0 = 0.f, a1 = 0.f, a2 = 0.f, a3 = 0.f;
                #pragma unroll
                for (int e4 = 0; e4 < 16; e4 += 4) {
                    float4 w0 = wr[e4 + 0], w1 = wr[e4 + 1], w2 = wr[e4 + 2], w3 = wr[e4 + 3];
                    a0 += x[e4 + 0].x * w0.x + x[e4 + 0].y * w0.y + x[e4 + 0].z * w0.z + x[e4 + 0].w * w0.w;
                    a1 += x[e4 + 1].x * w1.x + x[e4 + 1].y * w1.y + x[e4 + 1].z * w1.z + x[e4 + 1].w * w1.w;
                    a2 += x[e4 + 2].x * w2.x + x[e4 + 2].y * w2.y + x[e4 + 2].z * w2.z + x[e4 + 2].w * w2.w;
                    a3 += x[e4 + 3].x * w3.x + x[e4 + 3].y * w3.y + x[e4 + 3].z * w3.z + x[e4 + 3].w * w3.w;
                }
                r[dd] = (a0 + a1) + (a2 + a3);
            }
            float h0 = __bfloat162float(__float2bfloat16(r[0]));
            float h1 = __bfloat162float(__float2bfloat16(r[1]));
            float h2 = __bfloat162float(__float2bfloat16(r[2]));
            float h3 = __bfloat162float(__float2bfloat16(r[3]));
            qh[d4] = make_uint2(pkbf2(h0, h1), pkbf2(h2, h3));
            ql[d4] = make_uint2(pkbf2(r[0] - h0, r[1] - h1), pkbf2(r[2] - h2, r[3] - h3));
        }
    } else {
        // x1 split: 64 blocks, grid-stride over 262144 float4
        int idx = (blockIdx.x - 128) * 256 + tid;
        const float4* src = (const float4*)x1;
        uint2* ah = (uint2*)g_Ah;
        uint2* al = (uint2*)g_Al;
        #pragma unroll
        for (int it = 0; it < 16; ++it) {
            int i = it * 16384 + idx;
            float4 v = src[i];
            float hx = __bfloat162float(__float2bfloat16(v.x));
            float hy = __bfloat162float(__float2bfloat16(v.y));
            float hz = __bfloat162float(__float2bfloat16(v.z));
            float hw = __bfloat162float(__float2bfloat16(v.w));
            ah[i] = make_uint2(pkbf2(hx, hy), pkbf2(hz, hw));
            al[i] = make_uint2(pkbf2(v.x - hx, v.y - hy), pkbf2(v.z - hz, v.w - hw));
        }
    }
}

// ---------------------------------------------------------------------------
// Baseline-PTX tensor core helpers
// ---------------------------------------------------------------------------
__device__ __forceinline__ uint32_t smem_u32(const void* p) {
    uint32_t a;
    asm("{ .reg .u64 t; cvta.to.shared.u64 t, %1; cvt.u32.u64 %0, t; }" : "=r"(a) : "l"(p));
    return a;
}

__device__ __forceinline__ void ldsm4(uint32_t* r, uint32_t addr) {
    asm volatile("ldmatrix.sync.aligned.m8n8.x4.shared.b16 {%0,%1,%2,%3}, [%4];"
                 : "=r"(r[0]), "=r"(r[1]), "=r"(r[2]), "=r"(r[3]) : "r"(addr));
}

__device__ __forceinline__ void mma16816(float* c, const uint32_t* a,
                                         const uint32_t* b) {
    asm volatile(
        "mma.sync.aligned.m16n8k16.row.col.f32.bf16.bf16.f32 "
        "{%0,%1,%2,%3}, {%4,%5,%6,%7}, {%8,%9}, {%0,%1,%2,%3};"
        : "+f"(c[0]), "+f"(c[1]), "+f"(c[2]), "+f"(c[3])
        : "r"(a[0]), "r"(a[1]), "r"(a[2]), "r"(a[3]), "r"(b[0]), "r"(b[1]));
}

__device__ __forceinline__ void stcs2(float* p, float2 v) {
    asm volatile("st.global.cs.v2.f32 [%0], {%1,%2};" :: "l"(p), "f"(v.x), "f"(v.y)
                 : "memory");
}

__device__ __forceinline__ void cpasync16(uint32_t dst, const void* src) {
    asm volatile("cp.async.cg.shared.global [%0], [%1], 16;" :: "r"(dst), "l"(src)
                 : "memory");
}

// SMEM: 4 tiles of 128 rows x 72 bf16 (pitch 144B -> conflict-free ldmatrix)
#define PITCHB 144
#define TILEB  (128 * PITCHB)   // 18432
#define SM_AH  0
#define SM_AL  TILEB
#define SM_BH  (2 * TILEB)
#define SM_BL  (3 * TILEB)
#define SM_TOTAL (4 * TILEB)    // 73728 B

// ---------------------------------------------------------------------------
// Stage 2: out[s,i,j] = sum_d x1[s,i,d] * Q[s,j,d] via bf16x3 mma.sync.
// Operands pre-split in gmem; prologue is pure cp.async (no conversion).
// ---------------------------------------------------------------------------
__global__ __launch_bounds__(256, 2) void gemm_mma(const float* __restrict__ bias,
                                                   float* __restrict__ out) {
    extern __shared__ char smem[];
    const uint32_t sb = smem_u32(smem);
    const int tid = threadIdx.x, wid = tid >> 5, lid = tid & 31;
    const int s = blockIdx.z, bi = blockIdx.y, bj = blockIdx.x;
    const int warp_m = wid >> 1;   // 0..3, 32 rows
    const int warp_n = wid & 1;    // 0..1, 64 cols

    // ---- Prologue: 16 cp.async per thread ----
    const size_t Abase = ((size_t)s * NN + (size_t)bi * 128) * DD;
    const size_t Bbase = ((size_t)s * NN + (size_t)bj * 128) * DD;
    const __nv_bfloat16* srcs[4] = {g_Ah + Abase, g_Al + Abase,
                                    g_Bh + Bbase, g_Bl + Bbase};
    const uint32_t dsts[4] = {sb + SM_AH, sb + SM_AL, sb + SM_BH, sb + SM_BL};

    #pragma unroll
    for (int t = 0; t < 4; ++t) {
        #pragma unroll
        for (int it = 0; it < 4; ++it) {
            int idx = it * 256 + tid;        // 16B chunk id, 0..1023
            int row = idx >> 3;
            int c   = idx & 7;
            cpasync16(dsts[t] + (uint32_t)(row * PITCHB + c * 16),
                      srcs[t] + row * DD + c * 8);
        }
    }
    asm volatile("cp.async.commit_group;" ::: "memory");
    asm volatile("cp.async.wait_group 0;" ::: "memory");
    __syncthreads();

    // ---- Per-lane ldmatrix base addresses ----
    const uint32_t a_lane = (uint32_t)((warp_m * 32 + (lid & 15)) * PITCHB +
                                       ((lid >> 4) * 8) * 2);
    const uint32_t b_lane = (uint32_t)((warp_n * 64 + ((lid >> 4) & 1) * 8 + (lid & 7)) * PITCHB +
                                       (((lid >> 3) & 1) * 8) * 2);

    float acc[2][8][4];
    #pragma unroll
    for (int mt = 0; mt < 2; ++mt)
        #pragma unroll
        for (int nt = 0; nt < 8; ++nt)
            #pragma unroll
            for (int r = 0; r < 4; ++r) acc[mt][nt][r] = 0.f;

    const uint32_t pAh = sb + SM_AH + a_lane, pAl = sb + SM_AL + a_lane;
    const uint32_t pBh = sb + SM_BH + b_lane, pBl = sb + SM_BL + b_lane;

    // ---- Mainloop with fragment reuse: Ah*Bh, Al*Bh, Ah*Bl per k-step ----
    #pragma unroll
    for (int ks = 0; ks < 4; ++ks) {
        const uint32_t ko = (uint32_t)(ks * 32);
        uint32_t ah[2][4], al[2][4], bh[4][4], bl[4][4];
        #pragma unroll
        for (int mt = 0; mt < 2; ++mt)
            ldsm4(ah[mt], pAh + (uint32_t)(mt * 16 * PITCHB) + ko);
        #pragma unroll
        for (int nq = 0; nq < 4; ++nq)
            ldsm4(bh[nq], pBh + (uint32_t)(nq * 16 * PITCHB) + ko);
        #pragma unroll
        for (int mt = 0; mt < 2; ++mt)
            #pragma unroll
            for (int nq = 0; nq < 4; ++nq) {
                mma16816(acc[mt][2 * nq],     ah[mt], &bh[nq][0]);
                mma16816(acc[mt][2 * nq + 1], ah[mt], &bh[nq][2]);
            }
        #pragma unroll
        for (int mt = 0; mt < 2; ++mt)
            ldsm4(al[mt], pAl + (uint32_t)(mt * 16 * PITCHB) + ko);
        #pragma unroll
        for (int mt = 0; mt < 2; ++mt)
            #pragma unroll
            for (int nq = 0; nq < 4; ++nq) {
                mma16816(acc[mt][2 * nq],     al[mt], &bh[nq][0]);
                mma16816(acc[mt][2 * nq + 1], al[mt], &bh[nq][2]);
            }
        #pragma unroll
        for (int nq = 0; nq < 4; ++nq)
            ldsm4(bl[nq], pBl + (uint32_t)(nq * 16 * PITCHB) + ko);
        #pragma unroll
        for (int mt = 0; mt < 2; ++mt)
            #pragma unroll
            for (int nq = 0; nq < 4; ++nq) {
                mma16816(acc[mt][2 * nq],     ah[mt], &bl[nq][0]);
                mma16816(acc[mt][2 * nq + 1], ah[mt], &bl[nq][2]);
            }
    }

    // ---- Epilogue: direct register stores (streaming), both batch copies ----
    const float bv = *bias;
    const size_t BST = (size_t)SS * NN * NN;
    const size_t i_base = (size_t)bi * 128 + warp_m * 32 + (lid >> 2);
    const size_t j_base = (size_t)bj * 128 + warp_n * 64 + (lid & 3) * 2;

    #pragma unroll
    for (int mt = 0; mt < 2; ++mt) {
        #pragma unroll
        for (int nt = 0; nt < 8; ++nt) {
            float2 v0 = make_float2(acc[mt][nt][0] + bv, acc[mt][nt][1] + bv);
            float2 v1 = make_float2(acc[mt][nt][2] + bv, acc[mt][nt][3] + bv);
            float* d = out + ((size_t)s * NN + i_base + mt * 16) * NN + j_base + nt * 8;
            stcs2(d, v0);
            stcs2(d + 8 * NN, v1);
            stcs2(d + BST, v0);
            stcs2(d + BST + 8 * NN, v1);
        }
    }
}

// ---------------------------------------------------------------------------
// Launch
// ---------------------------------------------------------------------------
extern "C" void kernel_launch(void* const* d_in, const int* in_sizes, int n_in,
                              void* d_out, int out_size) {
    const float* x0   = (const float*)d_in[0];  // tensor0 (S,N,D)
    const float* x1   = (const float*)d_in[1];  // tensor1 (S,N,D)
    const float* W    = (const float*)d_in[2];  // kernel (D,D)
    const float* bias = (const float*)d_in[3];  // scalar
    float* out = (float*)d_out;                 // (2,S,N,N)

    prep_kernel<<<192, 256>>>(x0, x1, W);

    cudaFuncSetAttribute(gemm_mma, cudaFuncAttributeMaxDynamicSharedMemorySize, SM_TOTAL);
    dim3 grid(NN / 128, NN / 128, SS);
    gemm_mma<<<grid, 256, SM_TOTAL>>>(bias, out);
}